// round 17
// baseline (speedup 1.0000x reference)
#include <cuda_runtime.h>
#include <cstdint>

// ---------------- problem constants ----------------
#define MTOT 16384
#define KTOT 1024
#define NTOT 1024

#define TILE_BYTES 8192          /* one 128x64 int8 tile in g_wb */
#define KT 16                    /* k-tiles per full K */

#define NCTA 256                 /* one CTA per 64 m-rows */
#define THREADS 256

#define A_TILE 4096              /* 64 rows x 64 k int8, swizzled */
#define A_SMEM (KT * A_TILE)     /* 64 KB resident A */
#define B_STAGES 4
#define B_STAGE 8192             /* 128 n-rows x 64 k int8 */
#define SMEM_TOTAL (A_SMEM + B_STAGES * B_STAGE)   /* 96 KB */

#define GSTEPS 128               /* 8 nts x 16 kt */

#define WPREP_BLOCKS 256         /* 4 output channels per 256-thread block */

// ---------------- scratch (device globals; no allocation allowed) ----------------
__device__ __align__(16) unsigned char g_wb[(size_t)NTOT * KTOT];  // 1 MB int8, tiled+swizzled
__device__ float g_alpha[NTOT];
__device__ float g_beta[NTOT];

// Tile layout (works for 64- or 128-row tiles): rows r packed 2-per-128B row:
//   off(r, kc16) = (r>>1)*128 + ( (((r&1)<<6) | kc16) ^ (((r>>1)&7)<<4) )
__device__ __forceinline__ uint32_t tile_off(uint32_t r, uint32_t kc16) {
    uint32_t pr = r >> 1;
    return pr * 128u + (((((r & 1u) << 6) | kc16) ^ ((pr & 7u) << 4)));
}

// ---------------- PTX helpers (sm_80/sm_90 only; no 'a'-gated instructions) ----------------
__device__ __forceinline__ void cp16(uint32_t dst, const void* src) {
    asm volatile("cp.async.cg.shared.global [%0], [%1], 16;" :: "r"(dst), "l"(src));
}
__device__ __forceinline__ void cp_commit() {
    asm volatile("cp.async.commit_group;" ::: "memory");
}
__device__ __forceinline__ void cp_wait2() {
    asm volatile("cp.async.wait_group 2;" ::: "memory");
}
__device__ __forceinline__ void ldsm4(uint32_t& r0, uint32_t& r1, uint32_t& r2, uint32_t& r3,
                                      uint32_t addr) {
    asm volatile("ldmatrix.sync.aligned.m8n8.x4.shared.b16 {%0,%1,%2,%3}, [%4];"
                 : "=r"(r0), "=r"(r1), "=r"(r2), "=r"(r3) : "r"(addr));
}
__device__ __forceinline__ void mma_s8(int* c, const uint32_t* a, const uint32_t* b) {
    asm volatile(
        "mma.sync.aligned.m16n8k32.row.col.s32.s8.s8.s32 "
        "{%0,%1,%2,%3}, {%4,%5,%6,%7}, {%8,%9}, {%0,%1,%2,%3};"
        : "+r"(c[0]), "+r"(c[1]), "+r"(c[2]), "+r"(c[3])
        : "r"(a[0]), "r"(a[1]), "r"(a[2]), "r"(a[3]), "r"(b[0]), "r"(b[1]));
}
__device__ __forceinline__ void pdl_launch_dependents() {
    asm volatile("griddepcontrol.launch_dependents;" ::: "memory");
}
__device__ __forceinline__ void pdl_wait() {
    asm volatile("griddepcontrol.wait;" ::: "memory");
}

__device__ __forceinline__ int q8(float v, float inv, float zp) {
    // match reference: round(x * (1/s) + zp), half-even, then clamp
    float t = __fadd_rn(__fmul_rn(v, inv), zp);
    return (int)fminf(fmaxf(rintf(t), -128.0f), 127.0f);
}
__device__ __forceinline__ uint32_t pack4(int a, int b, int c, int d) {
    return (uint32_t)(a & 255) | ((uint32_t)(b & 255) << 8) |
           ((uint32_t)(c & 255) << 16) | ((uint32_t)(d & 255) << 24);
}

// ---------------- kernel 1: weight prep (releases GEMM grid immediately) ----------------
__global__ __launch_bounds__(256) void wprep_kernel(
    const int* __restrict__ w,
    const float* __restrict__ wscale,
    const float* __restrict__ act_scale,
    const float* __restrict__ act_zp,
    const float* __restrict__ bias)
{
    __shared__ int red[4][2];
    const int tid = threadIdx.x;
    pdl_launch_dependents();   // GEMM starts its quant phase (x only) right away
    const int s = tid >> 6, t = tid & 63;
    const int o = blockIdx.x * 4 + s;

    const int4* wr = reinterpret_cast<const int4*>(w + (size_t)o * KTOT + t * 16);
    int4 p0 = wr[0], p1 = wr[1], p2 = wr[2], p3 = wr[3];

    int sum = p0.x + p0.y + p0.z + p0.w + p1.x + p1.y + p1.z + p1.w
            + p2.x + p2.y + p2.z + p2.w + p3.x + p3.y + p3.z + p3.w;

    uint32_t pk[4];
    pk[0] = pack4(p0.x, p0.y, p0.z, p0.w);
    pk[1] = pack4(p1.x, p1.y, p1.z, p1.w);
    pk[2] = pack4(p2.x, p2.y, p2.z, p2.w);
    pk[3] = pack4(p3.x, p3.y, p3.z, p3.w);

    unsigned k0 = (unsigned)t << 4;
    unsigned ntile = (unsigned)o >> 7, nr = (unsigned)o & 127u;
    unsigned kt = k0 >> 6, kc = k0 & 63u;
    unsigned off = (ntile * 16u + kt) * TILE_BYTES + tile_off(nr, kc);
    *reinterpret_cast<uint4*>(g_wb + off) = *reinterpret_cast<uint4*>(pk);

#pragma unroll
    for (int d = 16; d > 0; d >>= 1) sum += __shfl_down_sync(0xffffffffu, sum, d);
    if ((t & 31) == 0) red[s][t >> 5] = sum;
    __syncthreads();
    if (t == 0) {
        int tot = red[s][0] + red[s][1];
        float alpha = wscale[o] * act_scale[0];
        g_alpha[o] = alpha;
        g_beta[o]  = bias[o] - act_zp[0] * (float)tot * alpha;
    }
}

// ---------------- kernel 2: fused quant-into-smem + int8 GEMM + dequant ----------------
// 256 CTAs (64 m-rows each, full N), 256 threads = 8 warps 2(m) x 4(n), warp 32x32.
// 2 CTAs/SM (96 KB smem, <=128 regs). Phase 1 quantizes A into resident smem
// (reads only x -> no dependency). Phase 2: 4-stage B ring over 128 (nts,kt) steps.
__global__ __launch_bounds__(THREADS, 2) void gemm_kernel(
    float* __restrict__ out,
    const float* __restrict__ x,
    const float* __restrict__ act_scale,
    const float* __restrict__ act_zp)
{
    extern __shared__ __align__(128) unsigned char smem[];
    const uint32_t Sa = (uint32_t)__cvta_generic_to_shared(smem);
    const uint32_t Sb = Sa + A_SMEM;

    const int tid = threadIdx.x, wid = tid >> 5, lid = tid & 31;
    const int wm = wid & 1, wn = wid >> 1;     // 2(m) x 4(n)
    const unsigned mth = blockIdx.x;           // 64-row m-slice index

    // ---- phase 1: quantize this CTA's 64x1024 A slice into resident smem ----
    {
        const float inv = 1.0f / act_scale[0];
        const float zp  = act_zp[0];
#pragma unroll 4
        for (int it = 0; it < 16; it++) {      // 4096 chunks / 256 threads
            unsigned c    = (unsigned)(it * 256 + tid);
            unsigned tile = c >> 8;             // 256 chunks per 4KB tile
            unsigned wo   = (c & 255u) << 4;    // within-tile byte offset
            unsigned pr   = wo >> 7;
            unsigned q16  = wo & 127u;
            unsigned lc   = q16 ^ ((pr & 7u) << 4);
            unsigned r    = (pr << 1) | (lc >> 6);
            unsigned kc   = lc & 48u;
            unsigned m    = mth * 64u + r;
            unsigned k0   = tile * 64u + kc;

            const float4* src = reinterpret_cast<const float4*>(x + (size_t)m * KTOT + k0);
            uint32_t pk[4];
#pragma unroll
            for (int j = 0; j < 4; j++) {
                float4 v = src[j];
                pk[j] = pack4(q8(v.x, inv, zp), q8(v.y, inv, zp),
                              q8(v.z, inv, zp), q8(v.w, inv, zp));
            }
            *reinterpret_cast<uint4*>(smem + tile * A_TILE + wo) = *reinterpret_cast<uint4*>(pk);
        }
    }
    __syncthreads();

    // ---- wait for wprep outputs (g_wb / alpha / beta) before touching them ----
    pdl_wait();

    // ---- ldmatrix per-lane offsets ----
    uint32_t aoff[2][2], boff[2][2];
    {
        const uint32_t amr = (uint32_t)(wm * 32 + (lid & 15));
        const uint32_t akc = (uint32_t)((lid >> 4) * 16);
#pragma unroll
        for (int f = 0; f < 2; f++)
#pragma unroll
            for (int ks = 0; ks < 2; ks++)
                aoff[f][ks] = tile_off(amr + f * 16u, (uint32_t)(ks * 32) + akc);

        const uint32_t bnr = (uint32_t)(wn * 32 + (lid & 7) + ((lid >> 4) << 3));
        const uint32_t bkc = (uint32_t)(((lid >> 3) & 1) * 16);
#pragma unroll
        for (int gg = 0; gg < 2; gg++)
#pragma unroll
            for (int ks = 0; ks < 2; ks++)
                boff[gg][ks] = tile_off(bnr + gg * 16u, (uint32_t)(ks * 32) + bkc);
    }

    int acc[2][4][4] = {};
    const int row = lid >> 2, colp = (lid & 3) << 1;

    // B stage copy for flat step g: nts = g>>4, kt = g&15; 8KB = 256 thr x 2 x 16B
#define ISSUE_B(g_)                                                               \
    do {                                                                          \
        const unsigned _g = (unsigned)(g_);                                       \
        const uint32_t _ds = Sb + (_g & 3u) * B_STAGE;                            \
        const unsigned char* _src = g_wb + (size_t)(((_g >> 4) * 16u + (_g & 15u))) * TILE_BYTES; \
        cp16(_ds + tid * 16u,           _src + tid * 16);                         \
        cp16(_ds + (tid + 256) * 16u,   _src + (tid + 256) * 16);                 \
    } while (0)

#pragma unroll
    for (int p = 0; p < B_STAGES - 1; p++) { ISSUE_B(p); cp_commit(); }

    for (int g = 0; g < GSTEPS; g++) {
        cp_wait2();
        __syncthreads();
        if (g + 3 < GSTEPS) ISSUE_B(g + 3);
        cp_commit();

        const int kt = g & 15;
        const uint32_t ba = Sa + (uint32_t)kt * A_TILE;
        const uint32_t bb = Sb + (uint32_t)(g & 3) * B_STAGE;

#pragma unroll
        for (int ks = 0; ks < 2; ks++) {
            uint32_t a[2][4], b[4][2];
#pragma unroll
            for (int f = 0; f < 2; f++)
                ldsm4(a[f][0], a[f][1], a[f][2], a[f][3], ba + aoff[f][ks]);
#pragma unroll
            for (int gg = 0; gg < 2; gg++)
                ldsm4(b[2 * gg][0], b[2 * gg][1], b[2 * gg + 1][0], b[2 * gg + 1][1],
                      bb + boff[gg][ks]);
#pragma unroll
            for (int f = 0; f < 2; f++)
#pragma unroll
                for (int q = 0; q < 4; q++)
                    mma_s8(acc[f][q], a[f], b[q]);
        }

        if (kt == 15) {
            // ---- epilogue for slab nts = g>>4 ----
            const int nts = g >> 4;
            const int ncol0 = nts * 128 + wn * 32 + colp;
            float2 al[4], be[4];
#pragma unroll
            for (int q = 0; q < 4; q++) {
                al[q] = *reinterpret_cast<const float2*>(&g_alpha[ncol0 + q * 8]);
                be[q] = *reinterpret_cast<const float2*>(&g_beta[ncol0 + q * 8]);
            }
#pragma unroll
            for (int f = 0; f < 2; f++) {
                const size_t m0 = (size_t)(mth * 64 + wm * 32 + f * 16 + row);
                float* o0 = out + m0 * NTOT + ncol0;
                float* o1 = o0 + 8 * NTOT;
#pragma unroll
                for (int q = 0; q < 4; q++) {
                    float2 v0, v1;
                    v0.x = (float)acc[f][q][0] * al[q].x + be[q].x;
                    v0.y = (float)acc[f][q][1] * al[q].y + be[q].y;
                    v1.x = (float)acc[f][q][2] * al[q].x + be[q].x;
                    v1.y = (float)acc[f][q][3] * al[q].y + be[q].y;
                    *reinterpret_cast<float2*>(o0 + q * 8) = v0;
                    *reinterpret_cast<float2*>(o1 + q * 8) = v1;
                }
            }
#pragma unroll
            for (int f = 0; f < 2; f++)
#pragma unroll
                for (int q = 0; q < 4; q++)
#pragma unroll
                    for (int e = 0; e < 4; e++)
                        acc[f][q][e] = 0;
        }
    }
#undef ISSUE_B
}

// ---------------- launch ----------------
extern "C" void kernel_launch(void* const* d_in, const int* in_sizes, int n_in,
                              void* d_out, int out_size)
{
    const float* x      = (const float*)d_in[0];
    const int*   w      = (const int*)d_in[1];
    const float* wscale = (const float*)d_in[2];
    const float* ascale = (const float*)d_in[3];
    const float* azp    = (const float*)d_in[4];
    const float* bias   = (const float*)d_in[5];
    float* out = (float*)d_out;

    cudaFuncSetAttribute(gemm_kernel, cudaFuncAttributeMaxDynamicSharedMemorySize, SMEM_TOTAL);

    wprep_kernel<<<WPREP_BLOCKS, 256>>>(w, wscale, ascale, azp, bias);

    // GEMM with PDL: quant phase (x only) runs immediately; pdl_wait before
    // any access to wprep outputs. Serial-equivalent correctness.
    cudaLaunchConfig_t cfg = {};
    cfg.gridDim = dim3(NCTA, 1, 1);
    cfg.blockDim = dim3(THREADS, 1, 1);
    cfg.dynamicSmemBytes = (size_t)SMEM_TOTAL;
    cfg.stream = 0;
    cudaLaunchAttribute attrs[1];
    attrs[0].id = cudaLaunchAttributeProgrammaticStreamSerialization;
    attrs[0].val.programmaticStreamSerializationAllowed = 1;
    cfg.attrs = attrs;
    cfg.numAttrs = 1;
    cudaLaunchKernelEx(&cfg, gemm_kernel, out, x, ascale, azp);
}